// round 7
// baseline (speedup 1.0000x reference)
#include <cuda_runtime.h>
#include <cuda_bf16.h>
#include <math.h>
#include <cstdint>

#define B_ 16
#define T_ 512
#define IDIM_ 320
#define CD_ 1024
#define GD_ 4096   // 4*CD
#define HD_ 1024
#define LAYERS_ 4
#define NBLK_ 128  // persistent grid: <= 148 SMs -> all co-resident

typedef unsigned long long ull;
typedef unsigned int uint;

// ---------------- scratch (static device globals; no runtime alloc) ----------------
__device__ float g_xg[(size_t)B_ * T_ * GD_];        // precomputed input gates
__device__ float g_hT[CD_ * B_];                     // h transposed: hT[cell][b]
__device__ ull   g_bar;                              // ticket barrier (monotonic)
__device__ __align__(16) __nv_bfloat16 g_ah[(size_t)B_ * T_ * CD_]; // A hi
__device__ __align__(16) __nv_bfloat16 g_al[(size_t)B_ * T_ * CD_]; // A lo
__device__ __align__(16) __nv_bfloat16 g_bh[(size_t)GD_ * CD_];     // B hi
__device__ __align__(16) __nv_bfloat16 g_bl[(size_t)GD_ * CD_];     // B lo

// ---------------- packed fp32x2 helpers (step kernel) ----------------
__device__ __forceinline__ ull fma2(ull a, ull b, ull c) {
    ull d;
    asm("fma.rn.f32x2 %0, %1, %2, %3;" : "=l"(d) : "l"(a), "l"(b), "l"(c));
    return d;
}
__device__ __forceinline__ ull add2(ull a, ull b) {
    ull d;
    asm("add.rn.f32x2 %0, %1, %2;" : "=l"(d) : "l"(a), "l"(b));
    return d;
}
__device__ __forceinline__ ull pack2(float x, float y) {
    ull d;
    asm("mov.b64 %0, {%1, %2};" : "=l"(d) : "f"(x), "f"(y));
    return d;
}
__device__ __forceinline__ float2 unpack2(ull v) {
    float2 r;
    asm("mov.b64 {%0, %1}, %2;" : "=f"(r.x), "=f"(r.y) : "l"(v));
    return r;
}
__device__ __forceinline__ float sigf(float x) { return 1.f / (1.f + expf(-x)); }

#define HSTRIDE 20   // padded row stride (floats) for transposed h in smem

// ---------------- bf16 split conversion (inputs / weights) ----------------
__global__ void __launch_bounds__(256) conv_split_kernel(
    const float* __restrict__ x, __nv_bfloat16* __restrict__ hi,
    __nv_bfloat16* __restrict__ lo, int n)
{
    int i = (blockIdx.x * 256 + threadIdx.x) * 2;
    if (i >= n) return;
    float2 v = *(const float2*)(x + i);
    __nv_bfloat162 h2, l2;
    h2.x = __float2bfloat16_rn(v.x);
    h2.y = __float2bfloat16_rn(v.y);
    l2.x = __float2bfloat16_rn(v.x - __bfloat162float(h2.x));
    l2.y = __float2bfloat16_rn(v.y - __bfloat162float(h2.y));
    *(__nv_bfloat162*)(hi + i) = h2;
    *(__nv_bfloat162*)(lo + i) = l2;
}

// ---------------- zero masked rows of the split activations (pre-projection) ----------------
__global__ void __launch_bounds__(128) mask_rows_kernel(
    __nv_bfloat16* __restrict__ ah, __nv_bfloat16* __restrict__ al,
    const int* __restrict__ ilens)
{
    const int row = blockIdx.x;          // 0..B*T-1
    const int t = row & (T_ - 1);
    const int b = row >> 9;
    if (t < ilens[b]) return;
    uint4 z = make_uint4(0, 0, 0, 0);
    uint4* pa = (uint4*)(ah + (size_t)row * CD_);
    uint4* pl = (uint4*)(al + (size_t)row * CD_);
#pragma unroll
    for (int i = threadIdx.x; i < 128; i += 128) { pa[i] = z; pl[i] = z; }
}

// ---------------- MMA helpers ----------------
__device__ __forceinline__ uint32_t smem_u32(const void* p) {
    uint32_t a;
    asm("{ .reg .u64 t; cvta.to.shared.u64 t, %1; cvt.u32.u64 %0, t; }" : "=r"(a) : "l"(p));
    return a;
}
__device__ __forceinline__ void ldmx4(uint& r0, uint& r1, uint& r2, uint& r3,
                                      uint32_t a) {
    asm volatile("ldmatrix.sync.aligned.m8n8.x4.shared.b16 {%0,%1,%2,%3}, [%4];"
                 : "=r"(r0), "=r"(r1), "=r"(r2), "=r"(r3) : "r"(a));
}
__device__ __forceinline__ void mma16816(float* d, const uint* a, uint b0, uint b1) {
    asm volatile(
        "mma.sync.aligned.m16n8k16.row.col.f32.bf16.bf16.f32 "
        "{%0,%1,%2,%3}, {%4,%5,%6,%7}, {%8,%9}, {%0,%1,%2,%3};"
        : "+f"(d[0]), "+f"(d[1]), "+f"(d[2]), "+f"(d[3])
        : "r"(a[0]), "r"(a[1]), "r"(a[2]), "r"(a[3]), "r"(b0), "r"(b1));
}
__device__ __forceinline__ void cpasync16(uint32_t dst, const void* src) {
    asm volatile("cp.async.cg.shared.global [%0], [%1], 16;"
                 :: "r"(dst), "l"(src) : "memory");
}

// ---------------- bf16x3 GEMM (NT), cp.async 4-stage pipeline ----------------
// C[m,n] = sum_k A[m,k]*B[n,k] (+b1[n]+b2[n]); 128x128 tile, BK=32, 256 threads,
// 8 warps (4 M x 2 N, warp tile 32x64). Virtual K''=3K: (Ah,Bh),(Al,Bh),(Ah,Bl).
// Dynamic smem: 4 stages x (A 128x40 bf16 + B 128x40 bf16) = 81920 B.
#define SPAD 40
#define STG_BYTES (128 * SPAD * 2)     // 10240 per operand per stage
#define GSMEM (4 * 2 * STG_BYTES)      // 81920
#define NSTAGE 4

template <int TANH>
__global__ void __launch_bounds__(256) gemm_bf16x3_kernel(
    const __nv_bfloat16* __restrict__ Ah, const __nv_bfloat16* __restrict__ Al,
    const __nv_bfloat16* __restrict__ Bh, const __nv_bfloat16* __restrict__ Bl,
    const float* __restrict__ b1, const float* __restrict__ b2,
    float* __restrict__ C, int M, int N, int K)
{
    extern __shared__ char smem[];
    const uint32_t sb = smem_u32(smem);

    const int tid  = threadIdx.x;
    const int lane = tid & 31;
    const int warp = tid >> 5;
    const int wm   = warp & 3;
    const int wn   = warp >> 2;
    const int m0 = blockIdx.y * 128;
    const int n0 = blockIdx.x * 128;

    const int srow = tid >> 1;           // 0..127
    const int scol = (tid & 1) * 16;     // 0 or 16 (bf16)

    const int perseg = K >> 5;
    const int nslab  = 3 * perseg;

    float acc[2][8][4];
#pragma unroll
    for (int i = 0; i < 2; ++i)
#pragma unroll
        for (int j = 0; j < 8; ++j)
#pragma unroll
            for (int q = 0; q < 4; ++q) acc[i][j][q] = 0.f;

    // issue all cp.async for slab s into stage buffer `buf`, then commit
    auto issue = [&](int s, int buf) {
        const int seg = s / perseg;
        const int kin = (s - seg * perseg) * 32;
        const __nv_bfloat16* Aseg = (seg == 1) ? Al : Ah;
        const __nv_bfloat16* Bseg = (seg == 2) ? Bl : Bh;
        const __nv_bfloat16* ga = Aseg + (size_t)(m0 + srow) * K + kin + scol;
        const __nv_bfloat16* gb = Bseg + (size_t)(n0 + srow) * K + kin + scol;
        const uint32_t da = sb + buf * (2 * STG_BYTES) + srow * (SPAD * 2) + scol * 2;
        const uint32_t db = da + STG_BYTES;
        cpasync16(da,      ga);
        cpasync16(da + 16, ga + 8);
        cpasync16(db,      gb);
        cpasync16(db + 16, gb + 8);
        asm volatile("cp.async.commit_group;" ::: "memory");
    };

    // prologue: fill first NSTAGE-1 stages
#pragma unroll
    for (int p = 0; p < NSTAGE - 1; ++p) issue(p, p);

    for (int s = 0; s < nslab; ++s) {
        asm volatile("cp.async.wait_group %0;" :: "n"(NSTAGE - 2) : "memory");
        __syncthreads();

        if (s + NSTAGE - 1 < nslab) issue(s + NSTAGE - 1, (s + NSTAGE - 1) & 3);

        const uint32_t ab = sb + (s & 3) * (2 * STG_BYTES);
        const uint32_t bb = ab + STG_BYTES;
        const int rq = lane & 15;
        const int cqb = ((lane >> 4) << 3);    // 0 or 8 (bf16 col)
#pragma unroll
        for (int kh = 0; kh < 2; ++kh) {
            const int cq = kh * 16 + cqb;
            uint af[2][4];
#pragma unroll
            for (int mi = 0; mi < 2; ++mi)
                ldmx4(af[mi][0], af[mi][1], af[mi][2], af[mi][3],
                      ab + (wm * 32 + mi * 16 + rq) * (SPAD * 2) + cq * 2);
            uint bf4[4][4];
#pragma unroll
            for (int nq = 0; nq < 4; ++nq)
                ldmx4(bf4[nq][0], bf4[nq][1], bf4[nq][2], bf4[nq][3],
                      bb + (wn * 64 + nq * 16 + rq) * (SPAD * 2) + cq * 2);
#pragma unroll
            for (int mi = 0; mi < 2; ++mi)
#pragma unroll
                for (int nq = 0; nq < 4; ++nq) {
                    mma16816(acc[mi][2 * nq],     af[mi], bf4[nq][0], bf4[nq][2]);
                    mma16816(acc[mi][2 * nq + 1], af[mi], bf4[nq][1], bf4[nq][3]);
                }
        }
        __syncthreads();
    }

    // epilogue: lane l holds c[r + {0,8}][c + {0,1}], r = l>>2, c = 2*(l&3)
    const int r   = lane >> 2;
    const int cq2 = (lane & 3) * 2;
#pragma unroll
    for (int mi = 0; mi < 2; ++mi) {
#pragma unroll
        for (int nj = 0; nj < 8; ++nj) {
            const int m1 = m0 + wm * 32 + mi * 16 + r;
            const int n1 = n0 + wn * 64 + nj * 8 + cq2;
            float bb0 = b1 ? __ldg(b1 + n1) : 0.f;
            float bb1 = b1 ? __ldg(b1 + n1 + 1) : 0.f;
            if (b2) { bb0 += __ldg(b2 + n1); bb1 += __ldg(b2 + n1 + 1); }
            float v0 = acc[mi][nj][0] + bb0;
            float v1 = acc[mi][nj][1] + bb1;
            float v2 = acc[mi][nj][2] + bb0;
            float v3 = acc[mi][nj][3] + bb1;
            if (TANH) { v0 = tanhf(v0); v1 = tanhf(v1); v2 = tanhf(v2); v3 = tanhf(v3); }
            *(float2*)(C + (size_t)m1 * N + n1)       = make_float2(v0, v1);
            *(float2*)(C + (size_t)(m1 + 8) * N + n1) = make_float2(v2, v3);
        }
    }
}

// ---------------- persistent LSTM layer kernel (512 threads, k-split warps) ----------------
// Writes h as bf16 hi/lo split directly (feeds next layer's GEMM); fp32 h kept in hT.
__global__ void __launch_bounds__(512) lstm_layer_kernel(
    const float* __restrict__ Whh,   // [4096,1024]
    const float* __restrict__ xg,    // [B*T,4096]
    __nv_bfloat16* __restrict__ yh,  // [B*T,1024] h hi
    __nv_bfloat16* __restrict__ yl,  // [B*T,1024] h lo
    float* __restrict__ hT)          // [1024,16]
{
    extern __shared__ float hs[];                    // [1024][HSTRIDE]
    ull* comb = (ull*)(hs + CD_ * HSTRIDE);          // [8*32] flat
    const int tid  = threadIdx.x;
    const int lane = tid & 31;
    const int warp = tid >> 5;                       // 0..15
    const int wc   = warp & 7;
    const int kh   = warp >> 3;
    const int cell = blockIdx.x * 8 + wc;
    const ull  G   = (ull)gridDim.x;

    const int koff = kh * 512;
    const float* w0p = Whh + (size_t)(0 * CD_ + cell) * CD_ + koff;
    const float* w1p = Whh + (size_t)(1 * CD_ + cell) * CD_ + koff;
    const float* w2p = Whh + (size_t)(2 * CD_ + cell) * CD_ + koff;
    const float* w3p = Whh + (size_t)(3 * CD_ + cell) * CD_ + koff;

    float creg = 0.f;

    for (int t = 0; t < T_; ++t) {
        float xgi = 0.f, xgf = 0.f, xgg = 0.f, xgo = 0.f;
        size_t orow = 0;
        if (kh == 0 && lane < B_) {
            orow = (size_t)(lane * T_ + t);
            const float* xr = xg + orow * GD_ + cell;
            xgi = __ldg(xr);
            xgf = __ldg(xr + CD_);
            xgg = __ldg(xr + 2 * CD_);
            xgo = __ldg(xr + 3 * CD_);
        }

        ull acc[32];
#pragma unroll
        for (int i = 0; i < 32; ++i) acc[i] = 0ULL;

        if (t > 0) {
            const float4* src = (const float4*)hT;
#pragma unroll 4
            for (int i = tid; i < CD_ * B_ / 4; i += 512) {
                float4 v = __ldcg(src + i);
                const int k  = i >> 2;
                const int bq = (i & 3) * 4;
                float* d = hs + k * HSTRIDE + bq;
                d[0] = v.x; d[1] = v.y; d[2] = v.z; d[3] = v.w;
            }
            __syncthreads();

#pragma unroll 1
            for (int j = 0; j < 4; ++j) {
                const int kb = j * 128 + lane;
#pragma unroll
                for (int kc = 0; kc < 4; ++kc) {
                    const int kk = kb + kc * 32;
                    const float w0 = __ldg(w0p + kk);
                    const float w1 = __ldg(w1p + kk);
                    const float w2 = __ldg(w2p + kk);
                    const float w3 = __ldg(w3p + kk);
                    const ull wp0 = pack2(w0, w0);
                    const ull wp1 = pack2(w1, w1);
                    const ull wp2 = pack2(w2, w2);
                    const ull wp3 = pack2(w3, w3);
                    const float* hrow = hs + (koff + kk) * HSTRIDE;
#pragma unroll
                    for (int bq = 0; bq < 4; ++bq) {
                        const ulonglong2 h2 = *(const ulonglong2*)(hrow + bq * 4);
                        const int i0 = (2 * bq) * 4;
                        const int i1 = (2 * bq + 1) * 4;
                        acc[i0+0] = fma2(wp0, h2.x, acc[i0+0]);
                        acc[i0+1] = fma2(wp1, h2.x, acc[i0+1]);
                        acc[i0+2] = fma2(wp2, h2.x, acc[i0+2]);
                        acc[i0+3] = fma2(wp3, h2.x, acc[i0+3]);
                        acc[i1+0] = fma2(wp0, h2.y, acc[i1+0]);
                        acc[i1+1] = fma2(wp1, h2.y, acc[i1+1]);
                        acc[i1+2] = fma2(wp2, h2.y, acc[i1+2]);
                        acc[i1+3] = fma2(wp3, h2.y, acc[i1+3]);
                    }
                }
            }
        }

#pragma unroll
        for (int s = 0; s < 5; ++s) {
            const int off = 16 >> s;
            const int n   = 16 >> s;
            const bool hi = (lane & off) != 0;
#pragma unroll
            for (int i = 0; i < n; ++i) {
                ull send = hi ? acc[i] : acc[i + n];
                ull r = __shfl_xor_sync(0xffffffffu, send, off);
                acc[i] = add2(hi ? acc[i + n] : acc[i], r);
            }
        }

        if (kh == 1) comb[wc * 32 + lane] = acc[0];
        __syncthreads();
        ull tot = acc[0];
        if (kh == 0) tot = add2(tot, comb[wc * 32 + lane]);

        const int srcl = (lane >> 1) * 4;
        const ull r0 = __shfl_sync(0xffffffffu, tot, srcl + 0);
        const ull r1 = __shfl_sync(0xffffffffu, tot, srcl + 1);
        const ull r2 = __shfl_sync(0xffffffffu, tot, srcl + 2);
        const ull r3 = __shfl_sync(0xffffffffu, tot, srcl + 3);

        if (kh == 0 && lane < B_) {
            const bool oddb = (lane & 1) != 0;
            const float2 p0 = unpack2(r0), p1 = unpack2(r1), p2 = unpack2(r2), p3 = unpack2(r3);
            const float gi = (oddb ? p0.y : p0.x) + xgi;
            const float gf = (oddb ? p1.y : p1.x) + xgf;
            const float gg = (oddb ? p2.y : p2.x) + xgg;
            const float go = (oddb ? p3.y : p3.x) + xgo;
            const float cn = sigf(gf) * creg + sigf(gi) * tanhf(gg);
            creg = cn;
            const float hn = sigf(go) * tanhf(cn);
            const __nv_bfloat16 hh = __float2bfloat16_rn(hn);
            yh[orow * CD_ + cell] = hh;
            yl[orow * CD_ + cell] = __float2bfloat16_rn(hn - __bfloat162float(hh));
            hT[cell * B_ + lane]  = hn;
        }

        __threadfence();
        __syncthreads();
        if (tid == 0) {
            ull x = atomicAdd(&g_bar, 1ULL);
            ull target = x - (x % G) + G;
            while (*(volatile ull*)&g_bar < target) { }
        }
        __syncthreads();
    }
}

// ---------------- ilens tail ----------------
__global__ void write_tail_kernel(float* __restrict__ out, const int* __restrict__ ilens,
                                  long long base, long long out_size) {
    int i = threadIdx.x;
    if (i < B_ && base + i < out_size) out[base + i] = (float)ilens[i];
}

// ---------------- launch ----------------
extern "C" void kernel_launch(void* const* d_in, const int* in_sizes, int n_in,
                              void* d_out, int out_size)
{
    const float* xpad  = (const float*)d_in[0];   // [B,T,IDIM]
    const float* Wih0  = (const float*)d_in[1];   // [4096,320]
    const float* WihR  = (const float*)d_in[2];   // [3,4096,1024]
    const float* Whh   = (const float*)d_in[3];   // [4,4096,1024]
    const float* bih   = (const float*)d_in[4];   // [4,4096]
    const float* bhh   = (const float*)d_in[5];   // [4,4096]
    const float* Wlast = (const float*)d_in[6];   // [1024,1024]
    const float* blast = (const float*)d_in[7];   // [1024]
    const int*   ilens = (const int*)d_in[8];     // [16]
    float* out = (float*)d_out;

    float *xg, *hT;
    __nv_bfloat16 *ah, *al, *bh, *bl;
    cudaGetSymbolAddress((void**)&xg, g_xg);
    cudaGetSymbolAddress((void**)&hT, g_hT);
    cudaGetSymbolAddress((void**)&ah, g_ah);
    cudaGetSymbolAddress((void**)&al, g_al);
    cudaGetSymbolAddress((void**)&bh, g_bh);
    cudaGetSymbolAddress((void**)&bl, g_bl);

    const int smem_step = CD_ * HSTRIDE * 4 + 8 * 32 * 8;
    cudaFuncSetAttribute(lstm_layer_kernel,
                         cudaFuncAttributeMaxDynamicSharedMemorySize, smem_step);
    cudaFuncSetAttribute(gemm_bf16x3_kernel<0>,
                         cudaFuncAttributeMaxDynamicSharedMemorySize, GSMEM);
    cudaFuncSetAttribute(gemm_bf16x3_kernel<1>,
                         cudaFuncAttributeMaxDynamicSharedMemorySize, GSMEM);

    const int M = B_ * T_;  // 8192

    for (int l = 0; l < LAYERS_; ++l) {
        const float* Bw = (l == 0) ? Wih0 : (WihR + (size_t)(l - 1) * GD_ * CD_);
        const int K = (l == 0) ? IDIM_ : CD_;

        if (l == 0) {   // layers >=1: A split written directly by lstm kernel
            int nA = M * K;
            conv_split_kernel<<<(nA / 2 + 255) / 256, 256>>>(xpad, ah, al, nA);
        }
        {
            int nB = GD_ * K;
            conv_split_kernel<<<(nB / 2 + 255) / 256, 256>>>(Bw, bh, bl, nB);
        }

        dim3 grid_xg(GD_ / 128, M / 128);
        gemm_bf16x3_kernel<0><<<grid_xg, 256, GSMEM>>>(ah, al, bh, bl,
                                                       bih + l * GD_, bhh + l * GD_,
                                                       xg, M, GD_, K);

        const float* Wl = Whh + (size_t)l * GD_ * CD_;
        lstm_layer_kernel<<<NBLK_, 512, smem_step>>>(Wl, xg, ah, al, hT);
    }

    // projection: zero padded rows of split activations, then GEMM with tanh
    {
        mask_rows_kernel<<<M, 128>>>(ah, al, ilens);
        int nB = HD_ * CD_;
        conv_split_kernel<<<(nB / 2 + 255) / 256, 256>>>(Wlast, bh, bl, nB);
        dim3 grid_p(HD_ / 128, M / 128);
        gemm_bf16x3_kernel<1><<<grid_p, 256, GSMEM>>>(ah, al, bh, bl, blast, nullptr,
                                                      out, M, HD_, CD_);
    }

    const long long base = (long long)B_ * T_ * HD_;  // 8388608
    if ((long long)out_size > base)
        write_tail_kernel<<<1, 32>>>(out, ilens, base, (long long)out_size);
}

// round 8
// speedup vs baseline: 1.0310x; 1.0310x over previous
#include <cuda_runtime.h>
#include <cuda_bf16.h>
#include <math.h>
#include <cstdint>

#define B_ 16
#define T_ 512
#define IDIM_ 320
#define CD_ 1024
#define GD_ 4096   // 4*CD
#define HD_ 1024
#define LAYERS_ 4
#define NBLK_ 128  // persistent grid: <= 148 SMs -> all co-resident

typedef unsigned long long ull;
typedef unsigned int uint;

// ---------------- scratch (static device globals; no runtime alloc) ----------------
__device__ float g_xg[(size_t)B_ * T_ * GD_];        // precomputed input gates
__device__ float g_hT[CD_ * B_];                     // h transposed: hT[cell][b]
__device__ ull   g_bar;                              // ticket barrier (monotonic)
__device__ __align__(16) __nv_bfloat16 g_ah[(size_t)B_ * T_ * CD_]; // A hi
__device__ __align__(16) __nv_bfloat16 g_al[(size_t)B_ * T_ * CD_]; // A lo
__device__ __align__(16) __nv_bfloat16 g_bh[(size_t)GD_ * CD_];     // B hi
__device__ __align__(16) __nv_bfloat16 g_bl[(size_t)GD_ * CD_];     // B lo

// ---------------- packed fp32x2 helpers (step kernel) ----------------
__device__ __forceinline__ ull fma2(ull a, ull b, ull c) {
    ull d;
    asm("fma.rn.f32x2 %0, %1, %2, %3;" : "=l"(d) : "l"(a), "l"(b), "l"(c));
    return d;
}
__device__ __forceinline__ ull add2(ull a, ull b) {
    ull d;
    asm("add.rn.f32x2 %0, %1, %2;" : "=l"(d) : "l"(a), "l"(b));
    return d;
}
__device__ __forceinline__ ull pack2(float x, float y) {
    ull d;
    asm("mov.b64 %0, {%1, %2};" : "=l"(d) : "f"(x), "f"(y));
    return d;
}
__device__ __forceinline__ float2 unpack2(ull v) {
    float2 r;
    asm("mov.b64 {%0, %1}, %2;" : "=f"(r.x), "=f"(r.y) : "l"(v));
    return r;
}
__device__ __forceinline__ float sigf(float x) { return 1.f / (1.f + expf(-x)); }

#define HSTRIDE 20   // padded row stride (floats) for transposed h in smem

// ---------------- bf16 split conversion (inputs / weights) ----------------
__global__ void __launch_bounds__(256) conv_split_kernel(
    const float* __restrict__ x, __nv_bfloat16* __restrict__ hi,
    __nv_bfloat16* __restrict__ lo, int n)
{
    int i = (blockIdx.x * 256 + threadIdx.x) * 2;
    if (i >= n) return;
    float2 v = *(const float2*)(x + i);
    __nv_bfloat162 h2, l2;
    h2.x = __float2bfloat16_rn(v.x);
    h2.y = __float2bfloat16_rn(v.y);
    l2.x = __float2bfloat16_rn(v.x - __bfloat162float(h2.x));
    l2.y = __float2bfloat16_rn(v.y - __bfloat162float(h2.y));
    *(__nv_bfloat162*)(hi + i) = h2;
    *(__nv_bfloat162*)(lo + i) = l2;
}

// ---------------- MMA helpers ----------------
__device__ __forceinline__ uint32_t smem_u32(const void* p) {
    uint32_t a;
    asm("{ .reg .u64 t; cvta.to.shared.u64 t, %1; cvt.u32.u64 %0, t; }" : "=r"(a) : "l"(p));
    return a;
}
__device__ __forceinline__ void ldmx4(uint& r0, uint& r1, uint& r2, uint& r3,
                                      uint32_t a) {
    asm volatile("ldmatrix.sync.aligned.m8n8.x4.shared.b16 {%0,%1,%2,%3}, [%4];"
                 : "=r"(r0), "=r"(r1), "=r"(r2), "=r"(r3) : "r"(a));
}
__device__ __forceinline__ void mma16816(float* d, const uint* a, uint b0, uint b1) {
    asm volatile(
        "mma.sync.aligned.m16n8k16.row.col.f32.bf16.bf16.f32 "
        "{%0,%1,%2,%3}, {%4,%5,%6,%7}, {%8,%9}, {%0,%1,%2,%3};"
        : "+f"(d[0]), "+f"(d[1]), "+f"(d[2]), "+f"(d[3])
        : "r"(a[0]), "r"(a[1]), "r"(a[2]), "r"(a[3]), "r"(b0), "r"(b1));
}

// ---------------- bf16x3 GEMM (NT): C = A*B^T + bias, fp32 accum ----------------
// Block tile 128(M) x 256(N), BK=32, 512 threads, 16 warps (4M x 4N, warp 32x64).
// Register-prefetch ping-pong smem, ONE __syncthreads per slab.
// Virtual K'' = 3K over segments (Ah,Bh),(Al,Bh),(Ah,Bl).
// Dead-tile logic: rows t >= ilens[b] are dead. TANH=0 (xg): skip dead tiles
// entirely. TANH=1 (projection): dead rows output tanh(bias).
// Smem layout (bytes): A0@0, A1@10240, B0@20480, B1@40960 -> 61440 total.
#define SPAD 40                      // bf16 row stride (80 B)
#define GSMEM 61440

template <int TANH>
__global__ void __launch_bounds__(512) gemm_bf16x3_kernel(
    const __nv_bfloat16* __restrict__ Ah, const __nv_bfloat16* __restrict__ Al,
    const __nv_bfloat16* __restrict__ Bh, const __nv_bfloat16* __restrict__ Bl,
    const float* __restrict__ b1, const float* __restrict__ b2,
    float* __restrict__ C, int M, int N, int K, const int* __restrict__ ilens)
{
    extern __shared__ char smem[];
    const uint32_t sb = smem_u32(smem);

    const int tid  = threadIdx.x;
    const int lane = tid & 31;
    const int warp = tid >> 5;       // 0..15
    const int wm   = warp & 3;       // 4 warps along M
    const int wn   = warp >> 2;      // 4 warps along N
    const int m0 = blockIdx.y * 128;
    const int n0 = blockIdx.x * 256;

    const int ilb = __ldg(ilens + (m0 >> 9));      // batch of this M-tile
    const bool tdead = (m0 & 511) >= ilb;
    if (!TANH && tdead) return;

    float acc[2][8][4];
#pragma unroll
    for (int i = 0; i < 2; ++i)
#pragma unroll
        for (int j = 0; j < 8; ++j)
#pragma unroll
            for (int q = 0; q < 4; ++q) acc[i][j][q] = 0.f;

    if (!tdead) {
        const int perseg = K >> 5;
        const int nslab  = 3 * perseg;

        // staging assignments
        const int arow  = tid >> 2;          // 0..127
        const int ascol = (tid & 3) * 8;     // 0,8,16,24 (bf16)
        const int brow  = tid >> 1;          // 0..255
        const int bscol = (tid & 1) * 16;    // 0,16 (bf16)

        uint4 pa, pb0, pb1;
        auto loadAB = [&](int s) {
            const int seg = s / perseg;
            const int kin = (s - seg * perseg) * 32;
            const __nv_bfloat16* Aseg = (seg == 1) ? Al : Ah;
            const __nv_bfloat16* Bseg = (seg == 2) ? Bl : Bh;
            pa  = *(const uint4*)(Aseg + (size_t)(m0 + arow) * K + kin + ascol);
            const __nv_bfloat16* gb = Bseg + (size_t)(n0 + brow) * K + kin + bscol;
            pb0 = *(const uint4*)gb;
            pb1 = *(const uint4*)(gb + 8);
        };
        auto storeAB = [&](int buf) {
            *(uint4*)(smem + buf * 10240 + arow * 80 + ascol * 2) = pa;
            char* bp = smem + 20480 + buf * 20480 + brow * 80 + bscol * 2;
            *(uint4*)bp        = pb0;
            *(uint4*)(bp + 16) = pb1;
        };

        loadAB(0);
        storeAB(0);
        __syncthreads();

        int buf = 0;
        const int rq  = lane & 15;
        const int cqb = (lane >> 4) << 3;
        for (int s = 0; s < nslab; ++s) {
            if (s + 1 < nslab) loadAB(s + 1);

            const uint32_t abase = sb + buf * 10240;
            const uint32_t bbase = sb + 20480 + buf * 20480;
#pragma unroll
            for (int kh = 0; kh < 2; ++kh) {
                const int cq = kh * 16 + cqb;
                uint af[2][4];
#pragma unroll
                for (int mi = 0; mi < 2; ++mi)
                    ldmx4(af[mi][0], af[mi][1], af[mi][2], af[mi][3],
                          abase + (wm * 32 + mi * 16 + rq) * 80 + cq * 2);
#pragma unroll
                for (int nq = 0; nq < 4; ++nq) {
                    uint bf0, bf1, bf2, bf3;
                    ldmx4(bf0, bf1, bf2, bf3,
                          bbase + (wn * 64 + nq * 16 + rq) * 80 + cq * 2);
#pragma unroll
                    for (int mi = 0; mi < 2; ++mi) {
                        mma16816(acc[mi][2 * nq],     af[mi], bf0, bf2);
                        mma16816(acc[mi][2 * nq + 1], af[mi], bf1, bf3);
                    }
                }
            }

            if (s + 1 < nslab) {
                storeAB(buf ^ 1);
                __syncthreads();
                buf ^= 1;
            }
        }
    }

    // epilogue: lane l holds c[r + {0,8}][c + {0,1}], r = l>>2, c = 2*(l&3)
    const int r   = lane >> 2;
    const int cq2 = (lane & 3) * 2;
#pragma unroll
    for (int mi = 0; mi < 2; ++mi) {
#pragma unroll
        for (int nj = 0; nj < 8; ++nj) {
            const int m1 = m0 + wm * 32 + mi * 16 + r;
            const int n1 = n0 + wn * 64 + nj * 8 + cq2;
            float bb0 = b1 ? __ldg(b1 + n1) : 0.f;
            float bb1 = b1 ? __ldg(b1 + n1 + 1) : 0.f;
            if (b2) { bb0 += __ldg(b2 + n1); bb1 += __ldg(b2 + n1 + 1); }
            float v0, v1, v2, v3;
            if (TANH) {
                const bool d0 = tdead || ((m1 & 511) >= ilb);
                const bool d8 = tdead || (((m1 + 8) & 511) >= ilb);
                v0 = d0 ? tanhf(bb0) : tanhf(acc[mi][nj][0] + bb0);
                v1 = d0 ? tanhf(bb1) : tanhf(acc[mi][nj][1] + bb1);
                v2 = d8 ? tanhf(bb0) : tanhf(acc[mi][nj][2] + bb0);
                v3 = d8 ? tanhf(bb1) : tanhf(acc[mi][nj][3] + bb1);
            } else {
                v0 = acc[mi][nj][0] + bb0;
                v1 = acc[mi][nj][1] + bb1;
                v2 = acc[mi][nj][2] + bb0;
                v3 = acc[mi][nj][3] + bb1;
            }
            *(float2*)(C + (size_t)m1 * N + n1)       = make_float2(v0, v1);
            *(float2*)(C + (size_t)(m1 + 8) * N + n1) = make_float2(v2, v3);
        }
    }
}

// ---------------- persistent LSTM layer kernel (512 threads, k-split warps) ----------------
// Writes h as bf16 hi/lo split directly (feeds next layer's GEMM); fp32 h kept in hT.
__global__ void __launch_bounds__(512) lstm_layer_kernel(
    const float* __restrict__ Whh,   // [4096,1024]
    const float* __restrict__ xg,    // [B*T,4096]
    __nv_bfloat16* __restrict__ yh,  // [B*T,1024] h hi
    __nv_bfloat16* __restrict__ yl,  // [B*T,1024] h lo
    float* __restrict__ hT)          // [1024,16]
{
    extern __shared__ float hs[];                    // [1024][HSTRIDE]
    ull* comb = (ull*)(hs + CD_ * HSTRIDE);          // [8*32] flat
    const int tid  = threadIdx.x;
    const int lane = tid & 31;
    const int warp = tid >> 5;                       // 0..15
    const int wc   = warp & 7;
    const int kh   = warp >> 3;
    const int cell = blockIdx.x * 8 + wc;
    const ull  G   = (ull)gridDim.x;

    const int koff = kh * 512;
    const float* w0p = Whh + (size_t)(0 * CD_ + cell) * CD_ + koff;
    const float* w1p = Whh + (size_t)(1 * CD_ + cell) * CD_ + koff;
    const float* w2p = Whh + (size_t)(2 * CD_ + cell) * CD_ + koff;
    const float* w3p = Whh + (size_t)(3 * CD_ + cell) * CD_ + koff;

    float creg = 0.f;

    for (int t = 0; t < T_; ++t) {
        float xgi = 0.f, xgf = 0.f, xgg = 0.f, xgo = 0.f;
        size_t orow = 0;
        if (kh == 0 && lane < B_) {
            orow = (size_t)(lane * T_ + t);
            const float* xr = xg + orow * GD_ + cell;
            xgi = __ldg(xr);
            xgf = __ldg(xr + CD_);
            xgg = __ldg(xr + 2 * CD_);
            xgo = __ldg(xr + 3 * CD_);
        }

        ull acc[32];
#pragma unroll
        for (int i = 0; i < 32; ++i) acc[i] = 0ULL;

        if (t > 0) {
            const float4* src = (const float4*)hT;
#pragma unroll 4
            for (int i = tid; i < CD_ * B_ / 4; i += 512) {
                float4 v = __ldcg(src + i);
                const int k  = i >> 2;
                const int bq = (i & 3) * 4;
                float* d = hs + k * HSTRIDE + bq;
                d[0] = v.x; d[1] = v.y; d[2] = v.z; d[3] = v.w;
            }
            __syncthreads();

#pragma unroll 1
            for (int j = 0; j < 4; ++j) {
                const int kb = j * 128 + lane;
#pragma unroll
                for (int kc = 0; kc < 4; ++kc) {
                    const int kk = kb + kc * 32;
                    const float w0 = __ldg(w0p + kk);
                    const float w1 = __ldg(w1p + kk);
                    const float w2 = __ldg(w2p + kk);
                    const float w3 = __ldg(w3p + kk);
                    const ull wp0 = pack2(w0, w0);
                    const ull wp1 = pack2(w1, w1);
                    const ull wp2 = pack2(w2, w2);
                    const ull wp3 = pack2(w3, w3);
                    const float* hrow = hs + (koff + kk) * HSTRIDE;
#pragma unroll
                    for (int bq = 0; bq < 4; ++bq) {
                        const ulonglong2 h2 = *(const ulonglong2*)(hrow + bq * 4);
                        const int i0 = (2 * bq) * 4;
                        const int i1 = (2 * bq + 1) * 4;
                        acc[i0+0] = fma2(wp0, h2.x, acc[i0+0]);
                        acc[i0+1] = fma2(wp1, h2.x, acc[i0+1]);
                        acc[i0+2] = fma2(wp2, h2.x, acc[i0+2]);
                        acc[i0+3] = fma2(wp3, h2.x, acc[i0+3]);
                        acc[i1+0] = fma2(wp0, h2.y, acc[i1+0]);
                        acc[i1+1] = fma2(wp1, h2.y, acc[i1+1]);
                        acc[i1+2] = fma2(wp2, h2.y, acc[i1+2]);
                        acc[i1+3] = fma2(wp3, h2.y, acc[i1+3]);
                    }
                }
            }
        }

#pragma unroll
        for (int s = 0; s < 5; ++s) {
            const int off = 16 >> s;
            const int n   = 16 >> s;
            const bool hi = (lane & off) != 0;
#pragma unroll
            for (int i = 0; i < n; ++i) {
                ull send = hi ? acc[i] : acc[i + n];
                ull r = __shfl_xor_sync(0xffffffffu, send, off);
                acc[i] = add2(hi ? acc[i + n] : acc[i], r);
            }
        }

        if (kh == 1) comb[wc * 32 + lane] = acc[0];
        __syncthreads();
        ull tot = acc[0];
        if (kh == 0) tot = add2(tot, comb[wc * 32 + lane]);

        const int srcl = (lane >> 1) * 4;
        const ull r0 = __shfl_sync(0xffffffffu, tot, srcl + 0);
        const ull r1 = __shfl_sync(0xffffffffu, tot, srcl + 1);
        const ull r2 = __shfl_sync(0xffffffffu, tot, srcl + 2);
        const ull r3 = __shfl_sync(0xffffffffu, tot, srcl + 3);

        if (kh == 0 && lane < B_) {
            const bool oddb = (lane & 1) != 0;
            const float2 p0 = unpack2(r0), p1 = unpack2(r1), p2 = unpack2(r2), p3 = unpack2(r3);
            const float gi = (oddb ? p0.y : p0.x) + xgi;
            const float gf = (oddb ? p1.y : p1.x) + xgf;
            const float gg = (oddb ? p2.y : p2.x) + xgg;
            const float go = (oddb ? p3.y : p3.x) + xgo;
            const float cn = sigf(gf) * creg + sigf(gi) * tanhf(gg);
            creg = cn;
            const float hn = sigf(go) * tanhf(cn);
            const __nv_bfloat16 hh = __float2bfloat16_rn(hn);
            yh[orow * CD_ + cell] = hh;
            yl[orow * CD_ + cell] = __float2bfloat16_rn(hn - __bfloat162float(hh));
            hT[cell * B_ + lane]  = hn;
        }

        __threadfence();
        __syncthreads();
        if (tid == 0) {
            ull x = atomicAdd(&g_bar, 1ULL);
            ull target = x - (x % G) + G;
            while (*(volatile ull*)&g_bar < target) { }
        }
        __syncthreads();
    }
}

// ---------------- ilens tail ----------------
__global__ void write_tail_kernel(float* __restrict__ out, const int* __restrict__ ilens,
                                  long long base, long long out_size) {
    int i = threadIdx.x;
    if (i < B_ && base + i < out_size) out[base + i] = (float)ilens[i];
}

// ---------------- launch ----------------
extern "C" void kernel_launch(void* const* d_in, const int* in_sizes, int n_in,
                              void* d_out, int out_size)
{
    const float* xpad  = (const float*)d_in[0];   // [B,T,IDIM]
    const float* Wih0  = (const float*)d_in[1];   // [4096,320]
    const float* WihR  = (const float*)d_in[2];   // [3,4096,1024]
    const float* Whh   = (const float*)d_in[3];   // [4,4096,1024]
    const float* bih   = (const float*)d_in[4];   // [4,4096]
    const float* bhh   = (const float*)d_in[5];   // [4,4096]
    const float* Wlast = (const float*)d_in[6];   // [1024,1024]
    const float* blast = (const float*)d_in[7];   // [1024]
    const int*   ilens = (const int*)d_in[8];     // [16]
    float* out = (float*)d_out;

    float *xg, *hT;
    __nv_bfloat16 *ah, *al, *bh, *bl;
    cudaGetSymbolAddress((void**)&xg, g_xg);
    cudaGetSymbolAddress((void**)&hT, g_hT);
    cudaGetSymbolAddress((void**)&ah, g_ah);
    cudaGetSymbolAddress((void**)&al, g_al);
    cudaGetSymbolAddress((void**)&bh, g_bh);
    cudaGetSymbolAddress((void**)&bl, g_bl);

    const int smem_step = CD_ * HSTRIDE * 4 + 8 * 32 * 8;
    cudaFuncSetAttribute(lstm_layer_kernel,
                         cudaFuncAttributeMaxDynamicSharedMemorySize, smem_step);
    cudaFuncSetAttribute(gemm_bf16x3_kernel<0>,
                         cudaFuncAttributeMaxDynamicSharedMemorySize, GSMEM);
    cudaFuncSetAttribute(gemm_bf16x3_kernel<1>,
                         cudaFuncAttributeMaxDynamicSharedMemorySize, GSMEM);

    const int M = B_ * T_;  // 8192

    for (int l = 0; l < LAYERS_; ++l) {
        const float* Bw = (l == 0) ? Wih0 : (WihR + (size_t)(l - 1) * GD_ * CD_);
        const int K = (l == 0) ? IDIM_ : CD_;

        if (l == 0) {   // layers >=1: A split written directly by lstm kernel
            int nA = M * K;
            conv_split_kernel<<<(nA / 2 + 255) / 256, 256>>>(xpad, ah, al, nA);
        }
        {
            int nB = GD_ * K;
            conv_split_kernel<<<(nB / 2 + 255) / 256, 256>>>(Bw, bh, bl, nB);
        }

        dim3 grid_xg(GD_ / 256, M / 128);
        gemm_bf16x3_kernel<0><<<grid_xg, 512, GSMEM>>>(ah, al, bh, bl,
                                                       bih + l * GD_, bhh + l * GD_,
                                                       xg, M, GD_, K, ilens);

        const float* Wl = Whh + (size_t)l * GD_ * CD_;
        lstm_layer_kernel<<<NBLK_, 512, smem_step>>>(Wl, xg, ah, al, hT);
    }

    // projection: dead rows (t >= ilens[b]) produce tanh(bias) directly in epilogue
    {
        int nB = HD_ * CD_;
        conv_split_kernel<<<(nB / 2 + 255) / 256, 256>>>(Wlast, bh, bl, nB);
        dim3 grid_p(HD_ / 256, M / 128);
        gemm_bf16x3_kernel<1><<<grid_p, 512, GSMEM>>>(ah, al, bh, bl, blast, nullptr,
                                                      out, M, HD_, CD_, ilens);
    }

    const long long base = (long long)B_ * T_ * HD_;  // 8388608
    if ((long long)out_size > base)
        write_tail_kernel<<<1, 32>>>(out, ilens, base, (long long)out_size);
}